// round 3
// baseline (speedup 1.0000x reference)
#include <cuda_runtime.h>
#include <math.h>

#define EPS 1e-5f

constexpr int Bn = 256;   // batch
constexpr int CT = 256;   // trunk channels
constexpr int CR = 192;   // reg channels
constexpr int CG = 64;    // gpool channels
constexpr int H = 19, W = 19, HW = 361;
constexpr int PY = 21, PX = 24;      // padded plane 21 x 24 (zero border, 16B-aligned rows)
constexpr int PP = PY * PX;          // 504 floats per padded channel plane
constexpr int CCH = 8;               // cin per smem stage
constexpr int NTHREADS = 320;        // 20 rows * 16 couts

// ---- scratch (device globals; no allocation allowed) ----
__device__ float g_act1p[Bn * CT * PP];        // mish(bn1(x)), zero-padded planes
__device__ float g_act2p[Bn * CR * PP];        // mish(bn2(reg+gpo)), zero-padded planes
__device__ float g_reg [Bn * CR * HW];         // conv1a raw output
__device__ float g_gp  [Bn * CG * HW];         // mish(bn1b(conv1b))
__device__ float g_gpo [Bn * CR];              // gpool @ w_lin.T
__device__ float g_w1t [8 * CT * 288];         // [chunk32][cin][k9][co16][pair2]
__device__ float g_w2t [8 * CR * 288];

__device__ __forceinline__ float mishf(float x) {
    // x * tanh(softplus(x)) == x * (t^2 + 2t) / (t^2 + 2t + 2), t = e^x
    if (x > 20.f) return x;
    float t = __expf(x);
    float u = fmaf(t, t, 2.f * t);
    return x * __fdividef(u, u + 2.f);
}

// ---- weight transforms: OIHW -> [chunk][cin][k][co*2+h], cout = chunk*32 + co + 16h ----
__global__ void k_wt1(const float* __restrict__ w1a, const float* __restrict__ w1b) {
    int i = blockIdx.x * blockDim.x + threadIdx.x;
    if (i >= 8 * CT * 288) return;
    int chunk = i / (CT * 288);
    int rem   = i % (CT * 288);
    int cin   = rem / 288;
    int r2    = rem % 288;
    int k     = r2 / 32;
    int j     = r2 % 32;
    int cout  = chunk * 32 + (j >> 1) + 16 * (j & 1);
    g_w1t[i] = (cout < CR) ? w1a[(cout * CT + cin) * 9 + k]
                           : w1b[((cout - CR) * CT + cin) * 9 + k];
}

__global__ void k_wt2(const float* __restrict__ w2) {
    int i = blockIdx.x * blockDim.x + threadIdx.x;
    if (i >= 8 * CR * 288) return;
    int chunk = i / (CR * 288);
    int rem   = i % (CR * 288);
    int cin   = rem / 288;
    int r2    = rem % 288;
    int k     = r2 / 32;
    int j     = r2 % 32;
    int cout  = chunk * 32 + (j >> 1) + 16 * (j & 1);
    g_w2t[i] = w2[(cout * CR + cin) * 9 + k];
}

// ---- stage 1: act1p = pad(mish(bn1(x))), one block per (img, c) plane ----
__global__ void k_pre(const float* __restrict__ x,
                      const float* __restrict__ g, const float* __restrict__ b,
                      const float* __restrict__ m, const float* __restrict__ v) {
    int bx  = blockIdx.x;
    int img = bx / CT, c = bx % CT;
    float sc = g[c] * rsqrtf(v[c] + EPS);
    float bs = fmaf(-m[c], sc, b[c]);
    const float* xp = x + (size_t)bx * HW;
    float* op = g_act1p + (size_t)bx * PP;
    for (int i = threadIdx.x; i < PP; i += blockDim.x) {
        int y = i / PX, xc = i % PX;
        float val = 0.f;
        if (y >= 1 && y <= H && xc >= 1 && xc <= W)
            val = mishf(fmaf(xp[(y - 1) * W + (xc - 1)], sc, bs));
        op[i] = val;
    }
}

// ---- stage 4: act2p = pad(mish(bn2(reg + gpo))) ----
__global__ void k_mid(const float* __restrict__ g, const float* __restrict__ b,
                      const float* __restrict__ m, const float* __restrict__ v) {
    int bx  = blockIdx.x;
    int img = bx / CR, c = bx % CR;
    float sc = g[c] * rsqrtf(v[c] + EPS);
    float bs = fmaf(-m[c], sc, b[c]);
    float gv = g_gpo[img * CR + c];
    const float* rp = g_reg + (size_t)bx * HW;
    float* op = g_act2p + (size_t)bx * PP;
    for (int i = threadIdx.x; i < PP; i += blockDim.x) {
        int y = i / PX, xc = i % PX;
        float val = 0.f;
        if (y >= 1 && y <= H && xc >= 1 && xc <= W)
            val = mishf(fmaf(rp[(y - 1) * W + (xc - 1)] + gv, sc, bs));
        op[i] = val;
    }
}

// ---- 3x3 SAME conv, direct fp32, 32 couts/block (2 per thread) ----
// MODE 0: in=act1p (CIN=256); cout<192 -> g_reg; cout>=192 -> mish(bn1b) -> g_gp
// MODE 1: in=act2p (CIN=192); out = conv + resid(x)
template <int CIN, int MODE>
__global__ __launch_bounds__(NTHREADS, 2)
void k_conv(const float* __restrict__ bg, const float* __restrict__ bb,
            const float* __restrict__ bm, const float* __restrict__ bv,
            const float* __restrict__ resid, float* __restrict__ outp) {
    __shared__ __align__(16) float s_in[CCH * PP];    // 8*504*4 = 16128 B
    __shared__ __align__(16) float s_w[CCH * 288];    //  8*288*4 =  9216 B

    const float* in = (MODE == 0) ? g_act1p : g_act2p;
    const float* wt = (MODE == 0) ? g_w1t : g_w2t;

    const int chunk = blockIdx.x;
    const int img   = blockIdx.y;
    const int tid   = threadIdx.x;
    const int row   = tid >> 4;
    const int co    = tid & 15;
    const bool active = (row < H);

    float acc[2][W];
#pragma unroll
    for (int x = 0; x < W; x++) { acc[0][x] = 0.f; acc[1][x] = 0.f; }

    const float4* src  = reinterpret_cast<const float4*>(in + (size_t)img * CIN * PP);
    const float4* wsrc = reinterpret_cast<const float4*>(wt + (size_t)chunk * CIN * 288);

    for (int cc = 0; cc < CIN; cc += CCH) {
        // straight float4 copies; borders were pre-zeroed in gmem
        const float4* s4 = src + cc * (PP / 4);
#pragma unroll 1
        for (int i = tid; i < CCH * PP / 4; i += NTHREADS)
            reinterpret_cast<float4*>(s_in)[i] = s4[i];
        const float4* w4 = wsrc + cc * 72;
#pragma unroll 1
        for (int i = tid; i < CCH * 72; i += NTHREADS)
            reinterpret_cast<float4*>(s_w)[i] = w4[i];
        __syncthreads();

        if (active) {
#pragma unroll 2
            for (int c = 0; c < CCH; c++) {
                const float* base = s_in + c * PP + row * PX;
                const float* wb   = s_w + c * 288 + co * 2;
#pragma unroll
                for (int ky = 0; ky < 3; ky++) {
                    float rr[24];
                    const float4* rp = reinterpret_cast<const float4*>(base + ky * PX);
#pragma unroll
                    for (int j = 0; j < 6; j++)
                        *reinterpret_cast<float4*>(&rr[4 * j]) = rp[j];
#pragma unroll
                    for (int kx = 0; kx < 3; kx++) {
                        float2 w = *reinterpret_cast<const float2*>(&wb[(ky * 3 + kx) * 32]);
#pragma unroll
                        for (int x = 0; x < W; x++) {
                            acc[0][x] = fmaf(w.x, rr[x + kx], acc[0][x]);
                            acc[1][x] = fmaf(w.y, rr[x + kx], acc[1][x]);
                        }
                    }
                }
            }
        }
        __syncthreads();
    }

    if (!active) return;
#pragma unroll
    for (int h = 0; h < 2; h++) {
        int cg = chunk * 32 + co + 16 * h;
        if (MODE == 0) {
            if (cg < CR) {
                float* p = g_reg + ((size_t)img * CR + cg) * HW + row * W;
#pragma unroll
                for (int x = 0; x < W; x++) p[x] = acc[h][x];
            } else {
                int c2 = cg - CR;
                float sc = bg[c2] * rsqrtf(bv[c2] + EPS);
                float bs = fmaf(-bm[c2], sc, bb[c2]);
                float* p = g_gp + ((size_t)img * CG + c2) * HW + row * W;
#pragma unroll
                for (int x = 0; x < W; x++) p[x] = mishf(fmaf(acc[h][x], sc, bs));
            }
        } else {
            size_t off = ((size_t)img * CT + cg) * HW + (size_t)row * W;
            const float* rx = resid + off;
            float* p = outp + off;
#pragma unroll
            for (int x = 0; x < W; x++) p[x] = acc[h][x] + rx[x];
        }
    }
}

// ---- gpool (mean, 0.5*mean, max over 19x19) + linear [192 x 192] ----
__global__ void k_gpool(const float* __restrict__ wlin) {
    int img  = blockIdx.x;
    int tid  = threadIdx.x;           // 256 threads
    int warp = tid / 32, lane = tid % 32;
    __shared__ float pooled[3 * CG];

    for (int c = warp; c < CG; c += 8) {
        const float* p = g_gp + ((size_t)img * CG + c) * HW;
        float s = 0.f, mx = -INFINITY;
        for (int i = lane; i < HW; i += 32) {
            float v = p[i];
            s += v;
            mx = fmaxf(mx, v);
        }
#pragma unroll
        for (int off = 16; off; off >>= 1) {
            s  += __shfl_down_sync(0xFFFFFFFFu, s, off);
            mx = fmaxf(mx, __shfl_down_sync(0xFFFFFFFFu, mx, off));
        }
        if (lane == 0) {
            float mean = s * (1.f / 361.f);
            pooled[c]          = mean;
            pooled[CG + c]     = mean * 0.5f;   // (sqrt(361)-14)/10
            pooled[2 * CG + c] = mx;
        }
    }
    __syncthreads();
    if (tid < CR) {
        float s = 0.f;
        const float* wr = wlin + tid * (3 * CG);
#pragma unroll 4
        for (int k = 0; k < 3 * CG; k++) s = fmaf(pooled[k], wr[k], s);
        g_gpo[img * CR + tid] = s;
    }
}

extern "C" void kernel_launch(void* const* d_in, const int* in_sizes, int n_in,
                              void* d_out, int out_size) {
    const float* x    = (const float*)d_in[0];
    const float* b1g  = (const float*)d_in[1];
    const float* b1b  = (const float*)d_in[2];
    const float* b1m  = (const float*)d_in[3];
    const float* b1v  = (const float*)d_in[4];
    const float* w1a  = (const float*)d_in[5];
    const float* w1b  = (const float*)d_in[6];
    const float* bgg  = (const float*)d_in[7];
    const float* bgb  = (const float*)d_in[8];
    const float* bgm  = (const float*)d_in[9];
    const float* bgv  = (const float*)d_in[10];
    const float* wlin = (const float*)d_in[11];
    const float* b2g  = (const float*)d_in[12];
    const float* b2b  = (const float*)d_in[13];
    const float* b2m  = (const float*)d_in[14];
    const float* b2v  = (const float*)d_in[15];
    const float* w2   = (const float*)d_in[16];
    float* out = (float*)d_out;

    k_wt1<<<(8 * CT * 288 + 255) / 256, 256>>>(w1a, w1b);
    k_wt2<<<(8 * CR * 288 + 255) / 256, 256>>>(w2);
    k_pre<<<Bn * CT, 128>>>(x, b1g, b1b, b1m, b1v);

    dim3 gconv(8, Bn);
    k_conv<CT, 0><<<gconv, NTHREADS>>>(bgg, bgb, bgm, bgv, nullptr, nullptr);
    k_gpool<<<Bn, 256>>>(wlin);
    k_mid<<<Bn * CR, 128>>>(b2g, b2b, b2m, b2v);
    k_conv<CR, 1><<<gconv, NTHREADS>>>(nullptr, nullptr, nullptr, nullptr, x, out);
}

// round 6
// speedup vs baseline: 1.3319x; 1.3319x over previous
#include <cuda_runtime.h>
#include <cstdint>
#include <math.h>

#define EPS 1e-5f

constexpr int Bn = 256, CT = 256, CR = 192, CG = 64;
constexpr int H = 19, W = 19, HW = 361;
constexpr int PY = 21, PX = 24, PP = PY * PX;   // padded plane 21x24=504

constexpr int NK1 = 72;   // 2304/32 K-chunks, conv1
constexpr int NK2 = 54;   // 1728/32 K-chunks, conv2

// smem tile geometry (floats), stride 36 = 16B aligned + conflict-free
constexpr int AST = 36, ABUF = 128 * AST;        // 4608 floats
constexpr int BST = 36, BBUF = 192 * BST;        // 6912 floats
constexpr int BUFF = ABUF + BBUF;                // 11520 floats per stage
constexpr int SMEMSZ = 2 * BUFF * 4;             // 92160 bytes dynamic

// ---- device scratch ----
__device__ float g_act1p[Bn * CT * PP];
__device__ float g_act2p[Bn * CR * PP];
__device__ float g_reg [Bn * CR * HW];
__device__ float g_gp  [Bn * CG * HW];
__device__ float g_gpo [Bn * CR];
__device__ float g_wA1 [2 * NK1 * 4096];  // [mt][kc][row128][k32] tf32
__device__ float g_wA2 [2 * NK2 * 4096];
__device__ int   g_ofs [NK1 * 32];        // im2col tap offsets

__device__ __forceinline__ float to_tf32(float x) {
    uint32_t u; asm("cvt.rn.tf32.f32 %0, %1;" : "=r"(u) : "f"(x));
    return __uint_as_float(u);
}
__device__ __forceinline__ float mishf(float x) {
    if (x > 20.f) return x;
    float t = __expf(x);
    float u = fmaf(t, t, 2.f * t);
    return x * __fdividef(u, u + 2.f);
}
__device__ __forceinline__ void mma_tf32(float* d, const float* a, const float* b) {
    asm volatile(
        "mma.sync.aligned.m16n8k8.row.col.f32.tf32.tf32.f32 "
        "{%0,%1,%2,%3}, {%4,%5,%6,%7}, {%8,%9}, {%0,%1,%2,%3};"
        : "+f"(d[0]), "+f"(d[1]), "+f"(d[2]), "+f"(d[3])
        : "r"(__float_as_uint(a[0])), "r"(__float_as_uint(a[1])),
          "r"(__float_as_uint(a[2])), "r"(__float_as_uint(a[3])),
          "r"(__float_as_uint(b[0])), "r"(__float_as_uint(b[1])));
}

// ---- init: tap offsets ----
__global__ void k_ofs() {
    int i = blockIdx.x * blockDim.x + threadIdx.x;
    if (i >= NK1 * 32) return;
    int ci = i / 9, r = i - ci * 9;
    g_ofs[i] = ci * PP + (r / 3) * PX + (r % 3) - (PX + 1);
}
// ---- weight prep -> [mt][kc][row][k] tf32 ----
__global__ void k_wA1(const float* __restrict__ w1a, const float* __restrict__ w1b) {
    int i = blockIdx.x * blockDim.x + threadIdx.x;
    if (i >= 2 * NK1 * 4096) return;
    int blk = i >> 12, q = i & 4095;
    int mt = blk / NK1, kc = blk % NK1;
    int row = q >> 5, k = q & 31;
    int K = kc * 32 + k, ci = K / 9, r = K - ci * 9;
    int cout = mt * 128 + row;
    float v = (cout < CR) ? w1a[(cout * CT + ci) * 9 + r]
                          : w1b[((cout - CR) * CT + ci) * 9 + r];
    g_wA1[i] = to_tf32(v);
}
__global__ void k_wA2(const float* __restrict__ w2) {
    int i = blockIdx.x * blockDim.x + threadIdx.x;
    if (i >= 2 * NK2 * 4096) return;
    int blk = i >> 12, q = i & 4095;
    int mt = blk / NK2, kc = blk % NK2;
    int row = q >> 5, k = q & 31;
    int K = kc * 32 + k, ci = K / 9, r = K - ci * 9;
    int cout = mt * 128 + row;
    g_wA2[i] = to_tf32(w2[(cout * CR + ci) * 9 + r]);
}

// ---- act prep (zero-padded planes, tf32-rounded) ----
__global__ void k_pre(const float* __restrict__ x,
                      const float* __restrict__ g, const float* __restrict__ b,
                      const float* __restrict__ m, const float* __restrict__ v) {
    int bx = blockIdx.x;
    int c = bx % CT;
    float sc = g[c] * rsqrtf(v[c] + EPS);
    float bs = fmaf(-m[c], sc, b[c]);
    const float* xp = x + (size_t)bx * HW;
    float* op = g_act1p + (size_t)bx * PP;
    for (int i = threadIdx.x; i < PP; i += blockDim.x) {
        int y = i / PX, xc = i % PX;
        float val = 0.f;
        if (y >= 1 && y <= H && xc >= 1 && xc <= W)
            val = to_tf32(mishf(fmaf(xp[(y - 1) * W + (xc - 1)], sc, bs)));
        op[i] = val;
    }
}
__global__ void k_mid(const float* __restrict__ g, const float* __restrict__ b,
                      const float* __restrict__ m, const float* __restrict__ v) {
    int bx = blockIdx.x;
    int img = bx / CR, c = bx % CR;
    float sc = g[c] * rsqrtf(v[c] + EPS);
    float bs = fmaf(-m[c], sc, b[c]);
    float gv = g_gpo[img * CR + c];
    const float* rp = g_reg + (size_t)bx * HW;
    float* op = g_act2p + (size_t)bx * PP;
    for (int i = threadIdx.x; i < PP; i += blockDim.x) {
        int y = i / PX, xc = i % PX;
        float val = 0.f;
        if (y >= 1 && y <= H && xc >= 1 && xc <= W)
            val = to_tf32(mishf(fmaf(rp[(y - 1) * W + (xc - 1)] + gv, sc, bs)));
        op[i] = val;
    }
}

// ---- tf32 mma.sync implicit-GEMM conv ----
// Grid: (ntile=2, mtile=2, img). Block 192 = 6 warps, warp grid 2(M)x3(N),
// warp tile 64x64. D[128 couts x 192 pixels], K chunked by 32.
// MODE 0: in = g_act1p / w = g_wA1; cout<192 -> g_reg; else mish(bn1b) -> g_gp
// MODE 1: in = g_act2p / w = g_wA2; out = conv + resid
template <int NK, int MODE>
__global__ __launch_bounds__(192)
void k_convtc(const float* __restrict__ bg, const float* __restrict__ bb,
              const float* __restrict__ bm, const float* __restrict__ bv,
              const float* __restrict__ resid, float* __restrict__ outp) {
    extern __shared__ float sm[];
    __shared__ int sofs[NK * 32];
    constexpr int CIN = NK * 32 / 9;

    // device-context references to device globals (host cannot pass these!)
    const float* gw  = (MODE == 0) ? g_wA1 : g_wA2;
    const float* gin = (MODE == 0) ? g_act1p : g_act2p;

    const int tid = threadIdx.x, lane = tid & 31, wid = tid >> 5;
    const int Nt = blockIdx.x, Mt = blockIdx.y, img = blockIdx.z;
    const int wm = wid & 1, wn = wid >> 1;            // warp grid 2x3
    const int lq = lane >> 2, lr = lane & 3;

    for (int i = tid; i < NK * 32; i += 192) sofs[i] = g_ofs[i];

    // im2col geometry for this thread's pixel row (j = tid)
    int p = Nt * 192 + tid;
    if (p > 360) p = 360;
    const int ctr = (p / 19 + 1) * PX + (p % 19 + 1);
    const float* actimg = gin + (size_t)img * CIN * PP;
    const float4* gwA4 = (const float4*)(gw) + (size_t)Mt * NK * 1024;

    float d[4][8][4];
#pragma unroll
    for (int mt = 0; mt < 4; mt++)
#pragma unroll
        for (int nt = 0; nt < 8; nt++)
#pragma unroll
            for (int e = 0; e < 4; e++) d[mt][nt][e] = 0.f;

    // ---- staging lambda (A copy + B gather) ----
    auto stage = [&](int kc, int buf) {
        float* As = sm + buf * BUFF;
        float* Bs = As + ABUF;
#pragma unroll 2
        for (int q = tid; q < 1024; q += 192) {
            int row = q >> 3, kk = (q & 7) << 2;
            *(float4*)(As + row * AST + kk) = gwA4[kc * 1024 + q];
        }
        const int* of = sofs + kc * 32;
        float* brow = Bs + tid * BST;
#pragma unroll
        for (int k4 = 0; k4 < 8; k4++) {
            float4 v;
            v.x = actimg[of[k4 * 4 + 0] + ctr];
            v.y = actimg[of[k4 * 4 + 1] + ctr];
            v.z = actimg[of[k4 * 4 + 2] + ctr];
            v.w = actimg[of[k4 * 4 + 3] + ctr];
            *(float4*)(brow + k4 * 4) = v;
        }
    };

    __syncthreads();            // sofs visible
    stage(0, 0);
    __syncthreads();

    for (int kc = 0; kc < NK; kc++) {
        const int buf = kc & 1;
        if (kc + 1 < NK) stage(kc + 1, buf ^ 1);

        const float* As = sm + buf * BUFF;
        const float* Bs = As + ABUF;
        const float* ap = As + (wm * 64 + lq) * AST + lr;
        const float* bp = Bs + (wn * 64 + lq) * BST + lr;

#pragma unroll
        for (int ks = 0; ks < 4; ks++) {
            float a[4][4], b[8][2];
#pragma unroll
            for (int mt = 0; mt < 4; mt++) {
                const float* q = ap + mt * (16 * AST) + ks * 8;
                a[mt][0] = q[0];
                a[mt][1] = q[8 * AST];
                a[mt][2] = q[4];
                a[mt][3] = q[8 * AST + 4];
            }
#pragma unroll
            for (int nt = 0; nt < 8; nt++) {
                const float* q = bp + nt * (8 * BST) + ks * 8;
                b[nt][0] = q[0];
                b[nt][1] = q[4];
            }
#pragma unroll
            for (int mt = 0; mt < 4; mt++)
#pragma unroll
                for (int nt = 0; nt < 8; nt++)
                    mma_tf32(d[mt][nt], a[mt], b[nt]);
        }
        __syncthreads();
    }

    // ---- epilogue ----
#pragma unroll
    for (int mt = 0; mt < 4; mt++) {
#pragma unroll
        for (int e2 = 0; e2 < 2; e2++) {
            int row = wm * 64 + mt * 16 + lq + e2 * 8;
            int cout = Mt * 128 + row;
            float sc = 0.f, bs = 0.f;
            if (MODE == 0 && cout >= CR) {
                int c2 = cout - CR;
                sc = bg[c2] * rsqrtf(bv[c2] + EPS);
                bs = fmaf(-bm[c2], sc, bb[c2]);
            }
#pragma unroll
            for (int nt = 0; nt < 8; nt++) {
#pragma unroll
                for (int e1 = 0; e1 < 2; e1++) {
                    int col = wn * 64 + nt * 8 + 2 * lr + e1;
                    int pp = Nt * 192 + col;
                    if (pp >= HW) continue;
                    float val = d[mt][nt][e2 * 2 + e1];
                    if (MODE == 0) {
                        if (cout < CR)
                            g_reg[((size_t)img * CR + cout) * HW + pp] = val;
                        else
                            g_gp[((size_t)img * CG + (cout - CR)) * HW + pp] =
                                mishf(fmaf(val, sc, bs));
                    } else {
                        size_t off = ((size_t)img * CT + cout) * HW + pp;
                        outp[off] = val + resid[off];
                    }
                }
            }
        }
    }
}

// ---- gpool + linear ----
__global__ void k_gpool(const float* __restrict__ wlin) {
    int img = blockIdx.x;
    int tid = threadIdx.x, warp = tid / 32, lane = tid % 32;
    __shared__ float pooled[3 * CG];
    for (int c = warp; c < CG; c += 8) {
        const float* p = g_gp + ((size_t)img * CG + c) * HW;
        float s = 0.f, mx = -INFINITY;
        for (int i = lane; i < HW; i += 32) {
            float v = p[i];
            s += v; mx = fmaxf(mx, v);
        }
#pragma unroll
        for (int off = 16; off; off >>= 1) {
            s += __shfl_down_sync(0xFFFFFFFFu, s, off);
            mx = fmaxf(mx, __shfl_down_sync(0xFFFFFFFFu, mx, off));
        }
        if (lane == 0) {
            float mean = s * (1.f / 361.f);
            pooled[c] = mean;
            pooled[CG + c] = mean * 0.5f;
            pooled[2 * CG + c] = mx;
        }
    }
    __syncthreads();
    if (tid < CR) {
        float s = 0.f;
        const float* wr = wlin + tid * (3 * CG);
#pragma unroll 4
        for (int k = 0; k < 3 * CG; k++) s = fmaf(pooled[k], wr[k], s);
        g_gpo[img * CR + tid] = s;
    }
}

extern "C" void kernel_launch(void* const* d_in, const int* in_sizes, int n_in,
                              void* d_out, int out_size) {
    const float* x    = (const float*)d_in[0];
    const float* b1g  = (const float*)d_in[1];
    const float* b1b  = (const float*)d_in[2];
    const float* b1m  = (const float*)d_in[3];
    const float* b1v  = (const float*)d_in[4];
    const float* w1a  = (const float*)d_in[5];
    const float* w1b  = (const float*)d_in[6];
    const float* bgg  = (const float*)d_in[7];
    const float* bgb  = (const float*)d_in[8];
    const float* bgm  = (const float*)d_in[9];
    const float* bgv  = (const float*)d_in[10];
    const float* wlin = (const float*)d_in[11];
    const float* b2g  = (const float*)d_in[12];
    const float* b2b  = (const float*)d_in[13];
    const float* b2m  = (const float*)d_in[14];
    const float* b2v  = (const float*)d_in[15];
    const float* w2   = (const float*)d_in[16];
    float* out = (float*)d_out;

    cudaFuncSetAttribute(k_convtc<NK1, 0>, cudaFuncAttributeMaxDynamicSharedMemorySize, SMEMSZ);
    cudaFuncSetAttribute(k_convtc<NK2, 1>, cudaFuncAttributeMaxDynamicSharedMemorySize, SMEMSZ);

    k_ofs<<<(NK1 * 32 + 255) / 256, 256>>>();
    k_wA1<<<(2 * NK1 * 4096 + 255) / 256, 256>>>(w1a, w1b);
    k_wA2<<<(2 * NK2 * 4096 + 255) / 256, 256>>>(w2);
    k_pre<<<Bn * CT, 128>>>(x, b1g, b1b, b1m, b1v);

    dim3 gconv(2, 2, Bn);
    k_convtc<NK1, 0><<<gconv, 192, SMEMSZ>>>(bgg, bgb, bgm, bgv, nullptr, nullptr);
    k_gpool<<<Bn, 256>>>(wlin);
    k_mid<<<Bn * CR, 128>>>(b2g, b2b, b2m, b2v);
    k_convtc<NK2, 1><<<gconv, 192, SMEMSZ>>>(nullptr, nullptr, nullptr, nullptr, x, out);
}

// round 7
// speedup vs baseline: 1.7095x; 1.2835x over previous
#include <cuda_runtime.h>
#include <cuda_fp16.h>
#include <cstdint>
#include <math.h>

#define EPS 1e-5f

constexpr int Bn = 256, CT = 256, CR = 192, CG = 64;
constexpr int H = 19, W = 19, HW = 361;
constexpr int PY = 21, PX = 24, PP = PY * PX;   // padded plane 21x24=504

constexpr int NK1 = 72;   // 2304/32 K-chunks, conv1
constexpr int NK2 = 54;   // 1728/32 K-chunks, conv2

// smem geometry in halves; stride 40 halves (80B) -> conflict-free frag LDS.32
constexpr int ASTH = 40, ABUFH = 128 * ASTH;     // 5120 halves
constexpr int BSTH = 40, BBUFH = 192 * BSTH;     // 7680 halves
constexpr int BUFH = ABUFH + BBUFH;              // 12800 halves / stage
constexpr int SMEMSZ = 2 * BUFH * 2;             // 51200 bytes dynamic

// ---- device scratch ----
__device__ __half g_act1p[Bn * CT * PP];   // fp16 padded planes
__device__ __half g_act2p[Bn * CR * PP];
__device__ float  g_reg [Bn * CR * HW];
__device__ float  g_gp  [Bn * CG * HW];
__device__ float  g_gpo [Bn * CR];
__device__ __half g_wA1 [2 * NK1 * 4096];  // [mt][kc][row128][k32] fp16
__device__ __half g_wA2 [2 * NK2 * 4096];
__device__ int    g_ofs [NK1 * 32];        // im2col tap offsets

__device__ __forceinline__ float mishf(float x) {
    if (x > 20.f) return x;
    float t = __expf(x);
    float u = fmaf(t, t, 2.f * t);
    return x * __fdividef(u, u + 2.f);
}
__device__ __forceinline__ void mma_f16(float* d, const uint32_t* a, const uint32_t* b) {
    asm volatile(
        "mma.sync.aligned.m16n8k16.row.col.f32.f16.f16.f32 "
        "{%0,%1,%2,%3}, {%4,%5,%6,%7}, {%8,%9}, {%0,%1,%2,%3};"
        : "+f"(d[0]), "+f"(d[1]), "+f"(d[2]), "+f"(d[3])
        : "r"(a[0]), "r"(a[1]), "r"(a[2]), "r"(a[3]), "r"(b[0]), "r"(b[1]));
}

// ---- init: tap offsets ----
__global__ void k_ofs() {
    int i = blockIdx.x * blockDim.x + threadIdx.x;
    if (i >= NK1 * 32) return;
    int ci = i / 9, r = i - ci * 9;
    g_ofs[i] = ci * PP + (r / 3) * PX + (r % 3) - (PX + 1);
}
// ---- weight prep -> [mt][kc][row][k] fp16 ----
__global__ void k_wA1(const float* __restrict__ w1a, const float* __restrict__ w1b) {
    int i = blockIdx.x * blockDim.x + threadIdx.x;
    if (i >= 2 * NK1 * 4096) return;
    int blk = i >> 12, q = i & 4095;
    int mt = blk / NK1, kc = blk % NK1;
    int row = q >> 5, k = q & 31;
    int K = kc * 32 + k, ci = K / 9, r = K - ci * 9;
    int cout = mt * 128 + row;
    float v = (cout < CR) ? w1a[(cout * CT + ci) * 9 + r]
                          : w1b[((cout - CR) * CT + ci) * 9 + r];
    g_wA1[i] = __float2half_rn(v);
}
__global__ void k_wA2(const float* __restrict__ w2) {
    int i = blockIdx.x * blockDim.x + threadIdx.x;
    if (i >= 2 * NK2 * 4096) return;
    int blk = i >> 12, q = i & 4095;
    int mt = blk / NK2, kc = blk % NK2;
    int row = q >> 5, k = q & 31;
    int K = kc * 32 + k, ci = K / 9, r = K - ci * 9;
    int cout = mt * 128 + row;
    g_wA2[i] = __float2half_rn(w2[(cout * CR + ci) * 9 + r]);
}

// ---- act prep: block (24,21), one thread per padded element, fp16 out ----
__global__ void k_pre(const float* __restrict__ x,
                      const float* __restrict__ g, const float* __restrict__ b,
                      const float* __restrict__ m, const float* __restrict__ v) {
    int bx = blockIdx.x;
    int c = bx % CT;
    float sc = g[c] * rsqrtf(v[c] + EPS);
    float bs = fmaf(-m[c], sc, b[c]);
    int xc = threadIdx.x, y = threadIdx.y;
    float val = 0.f;
    if (y >= 1 && y <= H && xc >= 1 && xc <= W)
        val = mishf(fmaf(x[(size_t)bx * HW + (y - 1) * W + (xc - 1)], sc, bs));
    g_act1p[(size_t)bx * PP + y * PX + xc] = __float2half_rn(val);
}
__global__ void k_mid(const float* __restrict__ g, const float* __restrict__ b,
                      const float* __restrict__ m, const float* __restrict__ v) {
    int bx = blockIdx.x;
    int img = bx / CR, c = bx % CR;
    float sc = g[c] * rsqrtf(v[c] + EPS);
    float bs = fmaf(-m[c], sc, b[c]);
    float gv = g_gpo[img * CR + c];
    int xc = threadIdx.x, y = threadIdx.y;
    float val = 0.f;
    if (y >= 1 && y <= H && xc >= 1 && xc <= W)
        val = mishf(fmaf(g_reg[(size_t)bx * HW + (y - 1) * W + (xc - 1)] + gv, sc, bs));
    g_act2p[(size_t)bx * PP + y * PX + xc] = __float2half_rn(val);
}

// ---- fp16 mma.sync implicit-GEMM conv ----
// Grid (ntile=2, mtile=2, img); 192 thr = 6 warps (2M x 3N), warp tile 64x64.
// K chunked by 32 = 2 k16 steps.
template <int NK, int MODE>
__global__ __launch_bounds__(192)
void k_convtc(const float* __restrict__ bg, const float* __restrict__ bb,
              const float* __restrict__ bm, const float* __restrict__ bv,
              const float* __restrict__ resid, float* __restrict__ outp) {
    extern __shared__ __half smh[];
    __shared__ int sofs[NK * 32];
    constexpr int CIN = NK * 32 / 9;

    const __half* gw  = (MODE == 0) ? g_wA1 : g_wA2;
    const __half* gin = (MODE == 0) ? g_act1p : g_act2p;

    const int tid = threadIdx.x, lane = tid & 31, wid = tid >> 5;
    const int Nt = blockIdx.x, Mt = blockIdx.y, img = blockIdx.z;
    const int wm = wid & 1, wn = wid >> 1;
    const int lq = lane >> 2, lr = lane & 3;

    for (int i = tid; i < NK * 32; i += 192) sofs[i] = g_ofs[i];

    int p = Nt * 192 + tid;
    if (p > 360) p = 360;
    const int ctr = (p / 19 + 1) * PX + (p % 19 + 1);
    const __half* actimg = gin + (size_t)img * CIN * PP;
    const int4* gwA4 = (const int4*)(gw) + (size_t)Mt * NK * 512;  // 512 int4/chunk

    float d[4][8][4];
#pragma unroll
    for (int mt = 0; mt < 4; mt++)
#pragma unroll
        for (int nt = 0; nt < 8; nt++)
#pragma unroll
            for (int e = 0; e < 4; e++) d[mt][nt][e] = 0.f;

    auto stage = [&](int kc, int buf) {
        __half* As = smh + buf * BUFH;
        __half* Bs = As + ABUFH;
        // A: 512 int4 (8 halves each); row = q>>2, koff = (q&3)*8
#pragma unroll 1
        for (int q = tid; q < 512; q += 192) {
            int row = q >> 2, ko = (q & 3) << 3;
            *(int4*)(As + row * ASTH + ko) = gwA4[kc * 512 + q];
        }
        // B: one pixel row per thread, 32 taps -> 16 uints -> 4 STS.128
        const int* of = sofs + kc * 32;
        uint32_t r[16];
#pragma unroll
        for (int k2 = 0; k2 < 16; k2++) {
            uint32_t lo = *(const uint16_t*)(actimg + of[k2 * 2 + 0] + ctr);
            uint32_t hi = *(const uint16_t*)(actimg + of[k2 * 2 + 1] + ctr);
            r[k2] = lo | (hi << 16);
        }
        uint32_t* brow = (uint32_t*)(Bs + tid * BSTH);
#pragma unroll
        for (int q = 0; q < 4; q++)
            *(uint4*)(brow + q * 4) = make_uint4(r[q * 4], r[q * 4 + 1], r[q * 4 + 2], r[q * 4 + 3]);
    };

    __syncthreads();
    stage(0, 0);
    __syncthreads();

    for (int kc = 0; kc < NK; kc++) {
        const int buf = kc & 1;
        if (kc + 1 < NK) stage(kc + 1, buf ^ 1);

        const __half* As = smh + buf * BUFH;
        const __half* Bs = As + ABUFH;

#pragma unroll
        for (int ks = 0; ks < 2; ks++) {
            uint32_t a[4][4], b[8][2];
            const __half* ap = As + (wm * 64 + lq) * ASTH + ks * 16 + 2 * lr;
            const __half* bp = Bs + (wn * 64 + lq) * BSTH + ks * 16 + 2 * lr;
#pragma unroll
            for (int mt = 0; mt < 4; mt++) {
                const __half* q = ap + mt * (16 * ASTH);
                a[mt][0] = *(const uint32_t*)(q);
                a[mt][1] = *(const uint32_t*)(q + 8 * ASTH);
                a[mt][2] = *(const uint32_t*)(q + 8);
                a[mt][3] = *(const uint32_t*)(q + 8 * ASTH + 8);
            }
#pragma unroll
            for (int nt = 0; nt < 8; nt++) {
                const __half* q = bp + nt * (8 * BSTH);
                b[nt][0] = *(const uint32_t*)(q);
                b[nt][1] = *(const uint32_t*)(q + 8);
            }
#pragma unroll
            for (int mt = 0; mt < 4; mt++)
#pragma unroll
                for (int nt = 0; nt < 8; nt++)
                    mma_f16(d[mt][nt], a[mt], b[nt]);
        }
        __syncthreads();
    }

    // ---- epilogue ----
#pragma unroll
    for (int mt = 0; mt < 4; mt++) {
#pragma unroll
        for (int e2 = 0; e2 < 2; e2++) {
            int row = wm * 64 + mt * 16 + lq + e2 * 8;
            int cout = Mt * 128 + row;
            float sc = 0.f, bs = 0.f;
            if (MODE == 0 && cout >= CR) {
                int c2 = cout - CR;
                sc = bg[c2] * rsqrtf(bv[c2] + EPS);
                bs = fmaf(-bm[c2], sc, bb[c2]);
            }
#pragma unroll
            for (int nt = 0; nt < 8; nt++) {
#pragma unroll
                for (int e1 = 0; e1 < 2; e1++) {
                    int col = wn * 64 + nt * 8 + 2 * lr + e1;
                    int pp = Nt * 192 + col;
                    if (pp >= HW) continue;
                    float val = d[mt][nt][e2 * 2 + e1];
                    if (MODE == 0) {
                        if (cout < CR)
                            g_reg[((size_t)img * CR + cout) * HW + pp] = val;
                        else
                            g_gp[((size_t)img * CG + (cout - CR)) * HW + pp] =
                                mishf(fmaf(val, sc, bs));
                    } else {
                        size_t off = ((size_t)img * CT + cout) * HW + pp;
                        outp[off] = val + resid[off];
                    }
                }
            }
        }
    }
}

// ---- gpool + linear ----
__global__ void k_gpool(const float* __restrict__ wlin) {
    int img = blockIdx.x;
    int tid = threadIdx.x, warp = tid / 32, lane = tid % 32;
    __shared__ float pooled[3 * CG];
    for (int c = warp; c < CG; c += 8) {
        const float* p = g_gp + ((size_t)img * CG + c) * HW;
        float s = 0.f, mx = -INFINITY;
        for (int i = lane; i < HW; i += 32) {
            float v = p[i];
            s += v; mx = fmaxf(mx, v);
        }
#pragma unroll
        for (int off = 16; off; off >>= 1) {
            s += __shfl_down_sync(0xFFFFFFFFu, s, off);
            mx = fmaxf(mx, __shfl_down_sync(0xFFFFFFFFu, mx, off));
        }
        if (lane == 0) {
            float mean = s * (1.f / 361.f);
            pooled[c] = mean;
            pooled[CG + c] = mean * 0.5f;
            pooled[2 * CG + c] = mx;
        }
    }
    __syncthreads();
    if (tid < CR) {
        float s = 0.f;
        const float* wr = wlin + tid * (3 * CG);
#pragma unroll 4
        for (int k = 0; k < 3 * CG; k++) s = fmaf(pooled[k], wr[k], s);
        g_gpo[img * CR + tid] = s;
    }
}

extern "C" void kernel_launch(void* const* d_in, const int* in_sizes, int n_in,
                              void* d_out, int out_size) {
    const float* x    = (const float*)d_in[0];
    const float* b1g  = (const float*)d_in[1];
    const float* b1b  = (const float*)d_in[2];
    const float* b1m  = (const float*)d_in[3];
    const float* b1v  = (const float*)d_in[4];
    const float* w1a  = (const float*)d_in[5];
    const float* w1b  = (const float*)d_in[6];
    const float* bgg  = (const float*)d_in[7];
    const float* bgb  = (const float*)d_in[8];
    const float* bgm  = (const float*)d_in[9];
    const float* bgv  = (const float*)d_in[10];
    const float* wlin = (const float*)d_in[11];
    const float* b2g  = (const float*)d_in[12];
    const float* b2b  = (const float*)d_in[13];
    const float* b2m  = (const float*)d_in[14];
    const float* b2v  = (const float*)d_in[15];
    const float* w2   = (const float*)d_in[16];
    float* out = (float*)d_out;

    cudaFuncSetAttribute(k_convtc<NK1, 0>, cudaFuncAttributeMaxDynamicSharedMemorySize, SMEMSZ);
    cudaFuncSetAttribute(k_convtc<NK2, 1>, cudaFuncAttributeMaxDynamicSharedMemorySize, SMEMSZ);

    k_ofs<<<(NK1 * 32 + 255) / 256, 256>>>();
    k_wA1<<<(2 * NK1 * 4096 + 255) / 256, 256>>>(w1a, w1b);
    k_wA2<<<(2 * NK2 * 4096 + 255) / 256, 256>>>(w2);
    k_pre<<<Bn * CT, dim3(PX, PY)>>>(x, b1g, b1b, b1m, b1v);

    dim3 gconv(2, 2, Bn);
    k_convtc<NK1, 0><<<gconv, 192, SMEMSZ>>>(bgg, bgb, bgm, bgv, nullptr, nullptr);
    k_gpool<<<Bn, 256>>>(wlin);
    k_mid<<<Bn * CR, dim3(PX, PY)>>>(b2g, b2b, b2m, b2v);
    k_convtc<NK2, 1><<<gconv, 192, SMEMSZ>>>(nullptr, nullptr, nullptr, nullptr, x, out);
}

// round 8
// speedup vs baseline: 1.7689x; 1.0347x over previous
#include <cuda_runtime.h>
#include <cuda_fp16.h>
#include <cstdint>
#include <math.h>

#define EPS 1e-5f

constexpr int Bn = 256, CT = 256, CR = 192, CG = 64;
constexpr int H = 19, W = 19, HW = 361;
constexpr int PY = 21, PX = 24, PP = PY * PX;   // padded plane 21x24=504

constexpr int NK1 = 72;   // 2304/32 K-chunks
constexpr int NK2 = 54;   // 1728/32

// smem (halves), stride 40 halves = 80B, conflict-free
constexpr int ASTH = 40, ABUFH = 128 * ASTH;     // 5120 halves
constexpr int BSTH = 40, BBUFH = 192 * BSTH;     // 7680 halves
constexpr int BUFH = ABUFH + BBUFH;              // 12800 halves/stage
constexpr int SMEMSZ = 2 * BUFH * 2;             // 51200 B dynamic

// ---- device scratch ----
__device__ __half g_act1p[Bn * CT * PP];
__device__ __half g_act2p[Bn * CR * PP];
__device__ float  g_reg [Bn * CR * HW];
__device__ float  g_gp  [Bn * CG * HW];
__device__ float  g_gpo [Bn * CR];
__device__ __half g_wA1 [2 * NK1 * 4096];
__device__ __half g_wA2 [2 * NK2 * 4096];
__device__ int    g_ofs [NK1 * 32];

__device__ __forceinline__ float mishf(float x) {
    if (x > 20.f) return x;
    float t = __expf(x);
    float u = fmaf(t, t, 2.f * t);
    return x * __fdividef(u, u + 2.f);
}
__device__ __forceinline__ void mma_f16(float* d, const uint32_t* a, const uint32_t* b) {
    asm volatile(
        "mma.sync.aligned.m16n8k16.row.col.f32.f16.f16.f32 "
        "{%0,%1,%2,%3}, {%4,%5,%6,%7}, {%8,%9}, {%0,%1,%2,%3};"
        : "+f"(d[0]), "+f"(d[1]), "+f"(d[2]), "+f"(d[3])
        : "r"(a[0]), "r"(a[1]), "r"(a[2]), "r"(a[3]), "r"(b[0]), "r"(b[1]));
}
__device__ __forceinline__ uint32_t smem_u32(const void* p) {
    uint32_t a;
    asm("{ .reg .u64 t; cvta.to.shared.u64 t, %1; cvt.u32.u64 %0, t; }" : "=r"(a) : "l"(p));
    return a;
}
__device__ __forceinline__ void ldmx4(uint32_t* r, uint32_t addr) {
    asm volatile("ldmatrix.sync.aligned.m8n8.x4.shared.b16 {%0,%1,%2,%3}, [%4];"
                 : "=r"(r[0]), "=r"(r[1]), "=r"(r[2]), "=r"(r[3]) : "r"(addr));
}

// ---- init: tap offsets ----
__global__ void k_ofs() {
    int i = blockIdx.x * blockDim.x + threadIdx.x;
    if (i >= NK1 * 32) return;
    int ci = i / 9, r = i - ci * 9;
    g_ofs[i] = ci * PP + (r / 3) * PX + (r % 3) - (PX + 1);
}
// ---- weight prep ----
__global__ void k_wA1(const float* __restrict__ w1a, const float* __restrict__ w1b) {
    int i = blockIdx.x * blockDim.x + threadIdx.x;
    if (i >= 2 * NK1 * 4096) return;
    int blk = i >> 12, q = i & 4095;
    int mt = blk / NK1, kc = blk % NK1;
    int row = q >> 5, k = q & 31;
    int K = kc * 32 + k, ci = K / 9, r = K - ci * 9;
    int cout = mt * 128 + row;
    float v = (cout < CR) ? w1a[(cout * CT + ci) * 9 + r]
                          : w1b[((cout - CR) * CT + ci) * 9 + r];
    g_wA1[i] = __float2half_rn(v);
}
__global__ void k_wA2(const float* __restrict__ w2) {
    int i = blockIdx.x * blockDim.x + threadIdx.x;
    if (i >= 2 * NK2 * 4096) return;
    int blk = i >> 12, q = i & 4095;
    int mt = blk / NK2, kc = blk % NK2;
    int row = q >> 5, k = q & 31;
    int K = kc * 32 + k, ci = K / 9, r = K - ci * 9;
    int cout = mt * 128 + row;
    g_wA2[i] = __float2half_rn(w2[(cout * CR + ci) * 9 + r]);
}

// ---- act prep: 128 threads per (img, channel) plane ----
__global__ void k_pre(const float* __restrict__ x,
                      const float* __restrict__ g, const float* __restrict__ b,
                      const float* __restrict__ m, const float* __restrict__ v) {
    int bx = blockIdx.x;
    int c = bx % CT;
    float sc = g[c] * rsqrtf(v[c] + EPS);
    float bs = fmaf(-m[c], sc, b[c]);
    const float* xp = x + (size_t)bx * HW;
    __half* op = g_act1p + (size_t)bx * PP;
    for (int i = threadIdx.x; i < PP; i += 128) {
        int y = i / PX, xc = i - y * PX;
        float val = 0.f;
        if (y >= 1 && y <= H && xc >= 1 && xc <= W)
            val = mishf(fmaf(xp[(y - 1) * W + (xc - 1)], sc, bs));
        op[i] = __float2half_rn(val);
    }
}
__global__ void k_mid(const float* __restrict__ g, const float* __restrict__ b,
                      const float* __restrict__ m, const float* __restrict__ v) {
    int bx = blockIdx.x;
    int img = bx / CR, c = bx % CR;
    float sc = g[c] * rsqrtf(v[c] + EPS);
    float bs = fmaf(-m[c], sc, b[c]);
    float gv = g_gpo[img * CR + c];
    const float* rp = g_reg + (size_t)bx * HW;
    __half* op = g_act2p + (size_t)bx * PP;
    for (int i = threadIdx.x; i < PP; i += 128) {
        int y = i / PX, xc = i - y * PX;
        float val = 0.f;
        if (y >= 1 && y <= H && xc >= 1 && xc <= W)
            val = mishf(fmaf(rp[(y - 1) * W + (xc - 1)] + gv, sc, bs));
        op[i] = __float2half_rn(val);
    }
}

// ---- fp16 implicit-GEMM conv: 256 thr = 8 warps (2M x 4N), warp tile 64x48 ----
template <int NK, int MODE>
__global__ __launch_bounds__(256)
void k_convtc(const float* __restrict__ bg, const float* __restrict__ bb,
              const float* __restrict__ bm, const float* __restrict__ bv,
              const float* __restrict__ resid, float* __restrict__ outp) {
    extern __shared__ __half smh[];
    __shared__ int sofs[NK * 32];
    constexpr int CIN = NK * 32 / 9;

    const __half* gw  = (MODE == 0) ? g_wA1 : g_wA2;
    const __half* gin = (MODE == 0) ? g_act1p : g_act2p;

    const int tid = threadIdx.x, lane = tid & 31, wid = tid >> 5;
    const int Nt = blockIdx.x, Mt = blockIdx.y, img = blockIdx.z;
    const int wm = wid & 1, wn = wid >> 1;       // 2M x 4N
    const int lq = lane >> 2, lr = lane & 3;

    for (int i = tid; i < NK * 32; i += 256) sofs[i] = g_ofs[i];

    int p = Nt * 192 + tid;                      // threads 0..191 gather B
    if (p > 360) p = 360;
    const int ctr = (p / 19 + 1) * PX + (p % 19 + 1);
    const __half* actimg = gin + (size_t)img * CIN * PP;
    const int4* gwA4 = (const int4*)(gw) + (size_t)Mt * NK * 512;

    // ldmatrix A base address (per lane), relative to As start:
    //   mat = lane>>3: [m0-7,k0-7],[m8-15,k0-7],[m0-7,k8-15],[m8-15,k8-15]
    const int amrow = wm * 64 + (lane & 7) + 8 * ((lane >> 3) & 1);
    const int amkof = 8 * (lane >> 4);
    const uint32_t smbase = smem_u32(smh);

    float d[4][6][4];
#pragma unroll
    for (int mt = 0; mt < 4; mt++)
#pragma unroll
        for (int nt = 0; nt < 6; nt++)
#pragma unroll
            for (int e = 0; e < 4; e++) d[mt][nt][e] = 0.f;

    auto stage = [&](int kc, int buf) {
        __half* As = smh + buf * BUFH;
        __half* Bs = As + ABUFH;
#pragma unroll
        for (int q = tid; q < 512; q += 256) {
            int row = q >> 2, ko = (q & 3) << 3;
            *(int4*)(As + row * ASTH + ko) = gwA4[kc * 512 + q];
        }
        if (tid < 192) {
            const int* of = sofs + kc * 32;
            uint32_t r[16];
#pragma unroll
            for (int k2 = 0; k2 < 16; k2++) {
                uint32_t lo = *(const uint16_t*)(actimg + of[k2 * 2 + 0] + ctr);
                uint32_t hi = *(const uint16_t*)(actimg + of[k2 * 2 + 1] + ctr);
                r[k2] = lo | (hi << 16);
            }
            uint32_t* brow = (uint32_t*)(Bs + tid * BSTH);
#pragma unroll
            for (int q = 0; q < 4; q++)
                *(uint4*)(brow + q * 4) =
                    make_uint4(r[q * 4], r[q * 4 + 1], r[q * 4 + 2], r[q * 4 + 3]);
        }
    };

    __syncthreads();
    stage(0, 0);
    __syncthreads();

    for (int kc = 0; kc < NK; kc++) {
        const int buf = kc & 1;
        if (kc + 1 < NK) stage(kc + 1, buf ^ 1);

        const uint32_t Asa = smbase + (buf * BUFH) * 2;
        const __half* Bs = smh + buf * BUFH + ABUFH;

#pragma unroll
        for (int ks = 0; ks < 2; ks++) {
            uint32_t a[4][4], b[6][2];
#pragma unroll
            for (int mt = 0; mt < 4; mt++)
                ldmx4(a[mt], Asa + ((amrow + mt * 16) * ASTH + ks * 16 + amkof) * 2);
#pragma unroll
            for (int nt = 0; nt < 6; nt++) {
                const __half* q = Bs + (wn * 48 + nt * 8 + lq) * BSTH + ks * 16 + 2 * lr;
                b[nt][0] = *(const uint32_t*)(q);
                b[nt][1] = *(const uint32_t*)(q + 8);
            }
#pragma unroll
            for (int mt = 0; mt < 4; mt++)
#pragma unroll
                for (int nt = 0; nt < 6; nt++)
                    mma_f16(d[mt][nt], a[mt], b[nt]);
        }
        __syncthreads();
    }

    // ---- epilogue ----
#pragma unroll
    for (int mt = 0; mt < 4; mt++) {
#pragma unroll
        for (int e2 = 0; e2 < 2; e2++) {
            int row = wm * 64 + mt * 16 + lq + e2 * 8;
            int cout = Mt * 128 + row;
            float sc = 0.f, bs = 0.f;
            if (MODE == 0 && cout >= CR) {
                int c2 = cout - CR;
                sc = bg[c2] * rsqrtf(bv[c2] + EPS);
                bs = fmaf(-bm[c2], sc, bb[c2]);
            }
#pragma unroll
            for (int nt = 0; nt < 6; nt++) {
#pragma unroll
                for (int e1 = 0; e1 < 2; e1++) {
                    int col = wn * 48 + nt * 8 + 2 * lr + e1;
                    int pp = Nt * 192 + col;
                    if (pp >= HW) continue;
                    float val = d[mt][nt][e2 * 2 + e1];
                    if (MODE == 0) {
                        if (cout < CR)
                            g_reg[((size_t)img * CR + cout) * HW + pp] = val;
                        else
                            g_gp[((size_t)img * CG + (cout - CR)) * HW + pp] =
                                mishf(fmaf(val, sc, bs));
                    } else {
                        size_t off = ((size_t)img * CT + cout) * HW + pp;
                        outp[off] = val + resid[off];
                    }
                }
            }
        }
    }
}

// ---- gpool + linear ----
__global__ void k_gpool(const float* __restrict__ wlin) {
    int img = blockIdx.x;
    int tid = threadIdx.x, warp = tid / 32, lane = tid % 32;
    __shared__ float pooled[3 * CG];
    for (int c = warp; c < CG; c += 8) {
        const float* p = g_gp + ((size_t)img * CG + c) * HW;
        float s = 0.f, mx = -INFINITY;
        for (int i = lane; i < HW; i += 32) {
            float v = p[i];
            s += v; mx = fmaxf(mx, v);
        }
#pragma unroll
        for (int off = 16; off; off >>= 1) {
            s += __shfl_down_sync(0xFFFFFFFFu, s, off);
            mx = fmaxf(mx, __shfl_down_sync(0xFFFFFFFFu, mx, off));
        }
        if (lane == 0) {
            float mean = s * (1.f / 361.f);
            pooled[c] = mean;
            pooled[CG + c] = mean * 0.5f;
            pooled[2 * CG + c] = mx;
        }
    }
    __syncthreads();
    if (tid < CR) {
        float s = 0.f;
        const float* wr = wlin + tid * (3 * CG);
#pragma unroll 4
        for (int k = 0; k < 3 * CG; k++) s = fmaf(pooled[k], wr[k], s);
        g_gpo[img * CR + tid] = s;
    }
}

extern "C" void kernel_launch(void* const* d_in, const int* in_sizes, int n_in,
                              void* d_out, int out_size) {
    const float* x    = (const float*)d_in[0];
    const float* b1g  = (const float*)d_in[1];
    const float* b1b  = (const float*)d_in[2];
    const float* b1m  = (const float*)d_in[3];
    const float* b1v  = (const float*)d_in[4];
    const float* w1a  = (const float*)d_in[5];
    const float* w1b  = (const float*)d_in[6];
    const float* bgg  = (const float*)d_in[7];
    const float* bgb  = (const float*)d_in[8];
    const float* bgm  = (const float*)d_in[9];
    const float* bgv  = (const float*)d_in[10];
    const float* wlin = (const float*)d_in[11];
    const float* b2g  = (const float*)d_in[12];
    const float* b2b  = (const float*)d_in[13];
    const float* b2m  = (const float*)d_in[14];
    const float* b2v  = (const float*)d_in[15];
    const float* w2   = (const float*)d_in[16];
    float* out = (float*)d_out;

    cudaFuncSetAttribute(k_convtc<NK1, 0>, cudaFuncAttributeMaxDynamicSharedMemorySize, SMEMSZ);
    cudaFuncSetAttribute(k_convtc<NK2, 1>, cudaFuncAttributeMaxDynamicSharedMemorySize, SMEMSZ);

    k_ofs<<<(NK1 * 32 + 255) / 256, 256>>>();
    k_wA1<<<(2 * NK1 * 4096 + 255) / 256, 256>>>(w1a, w1b);
    k_wA2<<<(2 * NK2 * 4096 + 255) / 256, 256>>>(w2);
    k_pre<<<Bn * CT, 128>>>(x, b1g, b1b, b1m, b1v);

    dim3 gconv(2, 2, Bn);
    k_convtc<NK1, 0><<<gconv, 256, SMEMSZ>>>(bgg, bgb, bgm, bgv, nullptr, nullptr);
    k_gpool<<<Bn, 256>>>(wlin);
    k_mid<<<Bn * CR, 128>>>(b2g, b2b, b2m, b2v);
    k_convtc<NK2, 1><<<gconv, 256, SMEMSZ>>>(nullptr, nullptr, nullptr, nullptr, x, out);
}

// round 9
// speedup vs baseline: 2.7411x; 1.5496x over previous
#include <cuda_runtime.h>
#include <cuda_fp16.h>
#include <cstdint>
#include <math.h>

#define EPS 1e-5f

constexpr int Bn = 256, CT = 256, CR = 192, CG = 64;
constexpr int H = 19, W = 19, HW = 361;
constexpr int PY = 21, PX = 24, PP = PY * PX;

constexpr int NK1 = 72;   // 2304/32 K-chunks
constexpr int NK2 = 54;   // 1728/32

constexpr int ASTH = 40, ABUFH = 128 * ASTH;     // 5120 halves
constexpr int BSTH = 40, BBUFH = 192 * BSTH;     // 7680 halves
constexpr int BUFH = ABUFH + BBUFH;
constexpr int SMEMSZ = 2 * BUFH * 2;             // 51200 B

// ---- device scratch ----
__device__ __half g_act1p[Bn * CT * PP];
__device__ __half g_act2p[Bn * CR * PP];
__device__ float  g_reg [Bn * CR * HW];
__device__ float  g_gp  [Bn * CG * HW];
__device__ float  g_gpo [Bn * CR];
__device__ __half g_wA1 [2 * NK1 * 4096];
__device__ __half g_wA2 [2 * NK2 * 4096];
__device__ int    g_ofs [NK1 * 32];

__device__ __forceinline__ float mishf(float x) {
    if (x > 20.f) return x;
    float t = __expf(x);
    float u = fmaf(t, t, 2.f * t);
    return x * __fdividef(u, u + 2.f);
}
__device__ __forceinline__ void mma_f16(float* d, const uint32_t* a, const uint32_t* b) {
    asm volatile(
        "mma.sync.aligned.m16n8k16.row.col.f32.f16.f16.f32 "
        "{%0,%1,%2,%3}, {%4,%5,%6,%7}, {%8,%9}, {%0,%1,%2,%3};"
        : "+f"(d[0]), "+f"(d[1]), "+f"(d[2]), "+f"(d[3])
        : "r"(a[0]), "r"(a[1]), "r"(a[2]), "r"(a[3]), "r"(b[0]), "r"(b[1]));
}
__device__ __forceinline__ uint32_t smem_u32(const void* p) {
    uint32_t a;
    asm("{ .reg .u64 t; cvta.to.shared.u64 t, %1; cvt.u32.u64 %0, t; }" : "=r"(a) : "l"(p));
    return a;
}
__device__ __forceinline__ void ldmx4(uint32_t* r, uint32_t addr) {
    asm volatile("ldmatrix.sync.aligned.m8n8.x4.shared.b16 {%0,%1,%2,%3}, [%4];"
                 : "=r"(r[0]), "=r"(r[1]), "=r"(r[2]), "=r"(r[3]) : "r"(addr));
}
__device__ __forceinline__ void cpa16(uint32_t dst, const void* src) {
    asm volatile("cp.async.cg.shared.global [%0], [%1], 16;" :: "r"(dst), "l"(src));
}
#define CP_COMMIT() asm volatile("cp.async.commit_group;" ::: "memory")
#define CP_WAIT0()  asm volatile("cp.async.wait_group 0;" ::: "memory")

// ---- weight prep (k_ofs merged in so conv1 is the 4th launch for ncu) ----
__global__ void k_wA1(const float* __restrict__ w1a, const float* __restrict__ w1b) {
    int i = blockIdx.x * blockDim.x + threadIdx.x;
    if (i < NK1 * 32) {
        int ci = i / 9, r = i - ci * 9;
        g_ofs[i] = ci * PP + (r / 3) * PX + (r % 3) - (PX + 1);
    }
    if (i >= 2 * NK1 * 4096) return;
    int blk = i >> 12, q = i & 4095;
    int mt = blk / NK1, kc = blk % NK1;
    int row = q >> 5, k = q & 31;
    int K = kc * 32 + k, ci = K / 9, r = K - ci * 9;
    int cout = mt * 128 + row;
    float v = (cout < CR) ? w1a[(cout * CT + ci) * 9 + r]
                          : w1b[((cout - CR) * CT + ci) * 9 + r];
    g_wA1[i] = __float2half_rn(v);
}
__global__ void k_wA2(const float* __restrict__ w2) {
    int i = blockIdx.x * blockDim.x + threadIdx.x;
    if (i >= 2 * NK2 * 4096) return;
    int blk = i >> 12, q = i & 4095;
    int mt = blk / NK2, kc = blk % NK2;
    int row = q >> 5, k = q & 31;
    int K = kc * 32 + k, ci = K / 9, r = K - ci * 9;
    int cout = mt * 128 + row;
    g_wA2[i] = __float2half_rn(w2[(cout * CR + ci) * 9 + r]);
}

// ---- act prep ----
__global__ void k_pre(const float* __restrict__ x,
                      const float* __restrict__ g, const float* __restrict__ b,
                      const float* __restrict__ m, const float* __restrict__ v) {
    int bx = blockIdx.x;
    int c = bx % CT;
    float sc = g[c] * rsqrtf(v[c] + EPS);
    float bs = fmaf(-m[c], sc, b[c]);
    const float* xp = x + (size_t)bx * HW;
    __half* op = g_act1p + (size_t)bx * PP;
    for (int i = threadIdx.x; i < PP; i += 128) {
        int y = i / PX, xc = i - y * PX;
        float val = 0.f;
        if (y >= 1 && y <= H && xc >= 1 && xc <= W)
            val = mishf(fmaf(xp[(y - 1) * W + (xc - 1)], sc, bs));
        op[i] = __float2half_rn(val);
    }
}
__global__ void k_mid(const float* __restrict__ g, const float* __restrict__ b,
                      const float* __restrict__ m, const float* __restrict__ v) {
    int bx = blockIdx.x;
    int img = bx / CR, c = bx % CR;
    float sc = g[c] * rsqrtf(v[c] + EPS);
    float bs = fmaf(-m[c], sc, b[c]);
    float gv = g_gpo[img * CR + c];
    const float* rp = g_reg + (size_t)bx * HW;
    __half* op = g_act2p + (size_t)bx * PP;
    for (int i = threadIdx.x; i < PP; i += 128) {
        int y = i / PX, xc = i - y * PX;
        float val = 0.f;
        if (y >= 1 && y <= H && xc >= 1 && xc <= W)
            val = mishf(fmaf(rp[(y - 1) * W + (xc - 1)] + gv, sc, bs));
        op[i] = __float2half_rn(val);
    }
}

// ---- fp16 implicit-GEMM conv: 8 warps (2M x 4N), warp tile 64x48 ----
template <int NK, int MODE>
__global__ __launch_bounds__(256)
void k_convtc(const float* __restrict__ bg, const float* __restrict__ bb,
              const float* __restrict__ bm, const float* __restrict__ bv,
              const float* __restrict__ resid, float* __restrict__ outp) {
    extern __shared__ __half smh[];
    __shared__ int sofs[NK * 32];
    constexpr int CIN = NK * 32 / 9;

    const __half* gw  = (MODE == 0) ? g_wA1 : g_wA2;
    const __half* gin = (MODE == 0) ? g_act1p : g_act2p;

    const int tid = threadIdx.x, lane = tid & 31, wid = tid >> 5;
    const int Nt = blockIdx.x, Mt = blockIdx.y, img = blockIdx.z;
    const int wm = wid & 1, wn = wid >> 1;
    const int lq = lane >> 2, lr = lane & 3;

    for (int i = tid; i < NK * 32; i += 256) sofs[i] = g_ofs[i];

    int p = Nt * 192 + tid;
    if (p > 360) p = 360;
    const int ctr = (p / 19 + 1) * PX + (p % 19 + 1);
    const __half* actimg = gin + (size_t)img * CIN * PP;
    const int4* gwA4 = (const int4*)(gw) + (size_t)Mt * NK * 512;

    const int amrow = wm * 64 + (lane & 7) + 8 * ((lane >> 3) & 1);
    const int amkof = 8 * (lane >> 4);
    // B ldmatrix lane geometry: n-offset and k-offset within pair group
    const int bnof = (lane & 7) + 8 * (lane >> 4);
    const int bkof = 8 * ((lane >> 3) & 1);
    const uint32_t smbase = smem_u32(smh);

    float d[4][6][4];
#pragma unroll
    for (int mt = 0; mt < 4; mt++)
#pragma unroll
        for (int nt = 0; nt < 6; nt++)
#pragma unroll
            for (int e = 0; e < 4; e++) d[mt][nt][e] = 0.f;

    uint32_t bregs[16];

    // A stage via cp.async (2x16B per thread)
    auto ldgA = [&](int kc, int buf) {
        uint32_t Asa = smbase + (buf * BUFH) * 2;
#pragma unroll
        for (int q = tid; q < 512; q += 256) {
            int row = q >> 2, ko = (q & 3) << 3;
            cpa16(Asa + (row * ASTH + ko) * 2, gwA4 + kc * 512 + q);
        }
    };
    // B gather into regs (tid<192)
    auto ldgB = [&](int kc) {
        const int* of = sofs + kc * 32;
#pragma unroll
        for (int k2 = 0; k2 < 16; k2++) {
            uint32_t lo = *(const uint16_t*)(actimg + of[k2 * 2 + 0] + ctr);
            uint32_t hi = *(const uint16_t*)(actimg + of[k2 * 2 + 1] + ctr);
            bregs[k2] = lo | (hi << 16);
        }
    };
    auto stsB = [&](int buf) {
        uint32_t* brow = (uint32_t*)(smh + buf * BUFH + ABUFH + tid * BSTH);
#pragma unroll
        for (int q = 0; q < 4; q++)
            *(uint4*)(brow + q * 4) =
                make_uint4(bregs[q * 4], bregs[q * 4 + 1], bregs[q * 4 + 2], bregs[q * 4 + 3]);
    };

    __syncthreads();            // sofs
    ldgA(0, 0); CP_COMMIT();
    if (tid < 192) { ldgB(0); }
    CP_WAIT0();
    if (tid < 192) stsB(0);
    __syncthreads();

    for (int kc = 0; kc < NK; kc++) {
        const int buf = kc & 1;
        if (kc + 1 < NK) {
            ldgA(kc + 1, buf ^ 1); CP_COMMIT();
            if (tid < 192) ldgB(kc + 1);
        }

        const uint32_t Asa = smbase + (buf * BUFH) * 2;
        const uint32_t Bsa = Asa + ABUFH * 2;

#pragma unroll
        for (int ks = 0; ks < 2; ks++) {
            uint32_t a[4][4], b[6][2];
#pragma unroll
            for (int mt = 0; mt < 4; mt++)
                ldmx4(a[mt], Asa + ((amrow + mt * 16) * ASTH + ks * 16 + amkof) * 2);
#pragma unroll
            for (int j = 0; j < 3; j++) {
                uint32_t r[4];
                ldmx4(r, Bsa + ((wn * 48 + 16 * j + bnof) * BSTH + ks * 16 + bkof) * 2);
                b[2 * j][0] = r[0]; b[2 * j][1] = r[1];
                b[2 * j + 1][0] = r[2]; b[2 * j + 1][1] = r[3];
            }
#pragma unroll
            for (int mt = 0; mt < 4; mt++)
#pragma unroll
                for (int nt = 0; nt < 6; nt++)
                    mma_f16(d[mt][nt], a[mt], b[nt]);
        }

        if (kc + 1 < NK) {
            if (tid < 192) stsB(buf ^ 1);
            CP_WAIT0();
        }
        __syncthreads();
    }

    // ---- epilogue ----
#pragma unroll
    for (int mt = 0; mt < 4; mt++) {
#pragma unroll
        for (int e2 = 0; e2 < 2; e2++) {
            int row = wm * 64 + mt * 16 + lq + e2 * 8;
            int cout = Mt * 128 + row;
            float sc = 0.f, bs = 0.f;
            if (MODE == 0 && cout >= CR) {
                int c2 = cout - CR;
                sc = bg[c2] * rsqrtf(bv[c2] + EPS);
                bs = fmaf(-bm[c2], sc, bb[c2]);
            }
#pragma unroll
            for (int nt = 0; nt < 6; nt++) {
#pragma unroll
                for (int e1 = 0; e1 < 2; e1++) {
                    int col = wn * 48 + nt * 8 + 2 * lr + e1;
                    int pp = Nt * 192 + col;
                    if (pp >= HW) continue;
                    float val = d[mt][nt][e2 * 2 + e1];
                    if (MODE == 0) {
                        if (cout < CR)
                            g_reg[((size_t)img * CR + cout) * HW + pp] = val;
                        else
                            g_gp[((size_t)img * CG + (cout - CR)) * HW + pp] =
                                mishf(fmaf(val, sc, bs));
                    } else {
                        size_t off = ((size_t)img * CT + cout) * HW + pp;
                        outp[off] = val + resid[off];
                    }
                }
            }
        }
    }
}

// ---- gpool + linear ----
__global__ void k_gpool(const float* __restrict__ wlin) {
    int img = blockIdx.x;
    int tid = threadIdx.x, warp = tid / 32, lane = tid % 32;
    __shared__ float pooled[3 * CG];
    for (int c = warp; c < CG; c += 8) {
        const float* p = g_gp + ((size_t)img * CG + c) * HW;
        float s = 0.f, mx = -INFINITY;
        for (int i = lane; i < HW; i += 32) {
            float v = p[i];
            s += v; mx = fmaxf(mx, v);
        }
#pragma unroll
        for (int off = 16; off; off >>= 1) {
            s += __shfl_down_sync(0xFFFFFFFFu, s, off);
            mx = fmaxf(mx, __shfl_down_sync(0xFFFFFFFFu, mx, off));
        }
        if (lane == 0) {
            float mean = s * (1.f / 361.f);
            pooled[c] = mean;
            pooled[CG + c] = mean * 0.5f;
            pooled[2 * CG + c] = mx;
        }
    }
    __syncthreads();
    if (tid < CR) {
        float s = 0.f;
        const float* wr = wlin + tid * (3 * CG);
#pragma unroll 4
        for (int k = 0; k < 3 * CG; k++) s = fmaf(pooled[k], wr[k], s);
        g_gpo[img * CR + tid] = s;
    }
}

extern "C" void kernel_launch(void* const* d_in, const int* in_sizes, int n_in,
                              void* d_out, int out_size) {
    const float* x    = (const float*)d_in[0];
    const float* b1g  = (const float*)d_in[1];
    const float* b1b  = (const float*)d_in[2];
    const float* b1m  = (const float*)d_in[3];
    const float* b1v  = (const float*)d_in[4];
    const float* w1a  = (const float*)d_in[5];
    const float* w1b  = (const float*)d_in[6];
    const float* bgg  = (const float*)d_in[7];
    const float* bgb  = (const float*)d_in[8];
    const float* bgm  = (const float*)d_in[9];
    const float* bgv  = (const float*)d_in[10];
    const float* wlin = (const float*)d_in[11];
    const float* b2g  = (const float*)d_in[12];
    const float* b2b  = (const float*)d_in[13];
    const float* b2m  = (const float*)d_in[14];
    const float* b2v  = (const float*)d_in[15];
    const float* w2   = (const float*)d_in[16];
    float* out = (float*)d_out;

    cudaFuncSetAttribute(k_convtc<NK1, 0>, cudaFuncAttributeMaxDynamicSharedMemorySize, SMEMSZ);
    cudaFuncSetAttribute(k_convtc<NK2, 1>, cudaFuncAttributeMaxDynamicSharedMemorySize, SMEMSZ);

    k_wA1<<<(2 * NK1 * 4096 + 255) / 256, 256>>>(w1a, w1b);
    k_wA2<<<(2 * NK2 * 4096 + 255) / 256, 256>>>(w2);
    k_pre<<<Bn * CT, 128>>>(x, b1g, b1b, b1m, b1v);

    dim3 gconv(2, 2, Bn);
    k_convtc<NK1, 0><<<gconv, 256, SMEMSZ>>>(bgg, bgb, bgm, bgv, nullptr, nullptr);
    k_gpool<<<Bn, 256>>>(wlin);
    k_mid<<<Bn * CR, 128>>>(b2g, b2b, b2m, b2v);
    k_convtc<NK2, 1><<<gconv, 256, SMEMSZ>>>(nullptr, nullptr, nullptr, nullptr, x, out);
}